// round 14
// baseline (speedup 1.0000x reference)
#include <cuda_runtime.h>
#include <cuda_fp16.h>
#include <math.h>
#include <stdint.h>

#define S 2048
#define H 1024
#define F 4096
#define E 8
#define CAP 512
#define BM 128
#define BN 128
#define BKT 32

// smem strides (bytes)
#define ASTB 80            // 32 halfs + 8 pad
#define BSTB 272           // 128 halfs + 8 pad
#define A_BYTES (BM * ASTB)            // 10240
#define STAGE (A_BYTES + BKT * BSTB)   // 18944
#define NSTAGE 4

__device__ float  g_gates[S * E];
__device__ int    g_idx1[S];
__device__ int    g_idx2[S];
__device__ int    g_slot_tok[E * CAP];
__device__ float  g_slot_w[E * CAP];
__device__ __half g_xh[(size_t)S * H];
__device__ __half g_w1h[(size_t)E * H * F];
__device__ __half g_w2h[(size_t)E * F * H];
__device__ __half g_h[(size_t)E * CAP * F];

// ---------------- helpers ----------------
__device__ __forceinline__ uint32_t smem_u32(const void* p) {
    uint32_t a;
    asm("{ .reg .u64 t; cvta.to.shared.u64 t, %1; cvt.u32.u64 %0, t; }" : "=r"(a) : "l"(p));
    return a;
}
__device__ __forceinline__ void cp16(uint32_t dst, const void* src) {
    asm volatile("cp.async.cg.shared.global [%0], [%1], 16;" :: "r"(dst), "l"(src));
}
__device__ __forceinline__ void cp16z(uint32_t dst, const void* src, int srcsize) {
    asm volatile("cp.async.cg.shared.global [%0], [%1], 16, %2;"
                 :: "r"(dst), "l"(src), "r"(srcsize));
}
__device__ __forceinline__ void cp_commit() {
    asm volatile("cp.async.commit_group;" ::: "memory");
}
template <int N> __device__ __forceinline__ void cp_wait() {
    asm volatile("cp.async.wait_group %0;" :: "n"(N) : "memory");
}
__device__ __forceinline__ void ldsm4(uint32_t* r, uint32_t a) {
    asm volatile("ldmatrix.sync.aligned.m8n8.x4.shared.b16 {%0,%1,%2,%3}, [%4];"
                 : "=r"(r[0]), "=r"(r[1]), "=r"(r[2]), "=r"(r[3]) : "r"(a));
}
__device__ __forceinline__ void ldsm4t(uint32_t* r, uint32_t a) {
    asm volatile("ldmatrix.sync.aligned.m8n8.x4.trans.shared.b16 {%0,%1,%2,%3}, [%4];"
                 : "=r"(r[0]), "=r"(r[1]), "=r"(r[2]), "=r"(r[3]) : "r"(a));
}
__device__ __forceinline__ void mma16816(float* c, const uint32_t* a, const uint32_t* b) {
    asm volatile(
        "mma.sync.aligned.m16n8k16.row.col.f32.f16.f16.f32 "
        "{%0,%1,%2,%3}, {%4,%5,%6,%7}, {%8,%9}, {%0,%1,%2,%3};"
        : "+f"(c[0]), "+f"(c[1]), "+f"(c[2]), "+f"(c[3])
        : "r"(a[0]), "r"(a[1]), "r"(a[2]), "r"(a[3]), "r"(b[0]), "r"(b[1]));
}
__device__ __forceinline__ float gelu_tanh(float v) {
    const float c = 0.7978845608028654f;
    float t = tanhf(c * (v + 0.044715f * v * v * v));
    return 0.5f * v * (1.0f + t);
}

// ---------------- fp32 -> fp16 convert (one tensor) ----------------
__global__ void cvt_one(const float4* __restrict__ src, uint2* __restrict__ dst, int n4) {
    int i = blockIdx.x * blockDim.x + threadIdx.x;
    if (i >= n4) return;
    float4 v = src[i];
    __half2 h0 = __floats2half2_rn(v.x, v.y);
    __half2 h1 = __floats2half2_rn(v.z, v.w);
    dst[i] = make_uint2(*reinterpret_cast<uint32_t*>(&h0), *reinterpret_cast<uint32_t*>(&h1));
}

// ---------------- init: slots -> -1, out -> 0 ----------------
__global__ void init_kernel(float4* __restrict__ out) {
    int i = blockIdx.x * blockDim.x + threadIdx.x;
    if (i < E * CAP) g_slot_tok[i] = -1;
    if (i < S * H / 4) out[i] = make_float4(0.f, 0.f, 0.f, 0.f);
}

// ---------------- gating: smem-transposed wg + float4 x ----------------
// 8 warps/block, warp = one token. wg cached in smem as [E][H].
__global__ void __launch_bounds__(256)
gate_kernel(const float* __restrict__ x, const float* __restrict__ wg) {
    __shared__ float swg[E * H];   // 32 KB, transposed [e][k]
    int tid = threadIdx.x;
    for (int i = tid; i < H * E; i += 256) {
        int k = i >> 3, e = i & 7;
        swg[e * H + k] = wg[i];
    }
    __syncthreads();

    int warp = blockIdx.x * 8 + (tid >> 5);
    int lane = tid & 31;
    const float4* xr4 = (const float4*)(x + (size_t)warp * H);
    uint2* xhr4 = (uint2*)(g_xh + (size_t)warp * H);

    float acc[E];
#pragma unroll
    for (int e = 0; e < E; e++) acc[e] = 0.0f;
#pragma unroll
    for (int it = 0; it < H / 128; it++) {
        int k4 = it * 32 + lane;
        float4 v = xr4[k4];
        __half2 h0 = __floats2half2_rn(v.x, v.y);
        __half2 h1 = __floats2half2_rn(v.z, v.w);
        xhr4[k4] = make_uint2(*reinterpret_cast<uint32_t*>(&h0),
                              *reinterpret_cast<uint32_t*>(&h1));
        int kk = 4 * k4;
#pragma unroll
        for (int e = 0; e < E; e++) {
            float4 wv = *reinterpret_cast<const float4*>(swg + e * H + kk);
            acc[e] += v.x * wv.x + v.y * wv.y + v.z * wv.z + v.w * wv.w;
        }
    }
#pragma unroll
    for (int off = 16; off > 0; off >>= 1)
#pragma unroll
        for (int e = 0; e < E; e++)
            acc[e] += __shfl_down_sync(0xffffffffu, acc[e], off);
    if (lane == 0) {
        float mx = acc[0];
#pragma unroll
        for (int e = 1; e < E; e++) mx = fmaxf(mx, acc[e]);
        float g[E], sum = 0.0f;
#pragma unroll
        for (int e = 0; e < E; e++) { g[e] = expf(acc[e] - mx); sum += g[e]; }
        float inv = 1.0f / sum;
        int i1 = 0; float v1 = acc[0];
#pragma unroll
        for (int e = 1; e < E; e++) if (acc[e] > v1) { v1 = acc[e]; i1 = e; }
        int i2 = -1; float v2 = -3.4e38f;
#pragma unroll
        for (int e = 0; e < E; e++)
            if (e != i1 && acc[e] > v2) { v2 = acc[e]; i2 = e; }
#pragma unroll
        for (int e = 0; e < E; e++) g_gates[warp * E + e] = g[e] * inv;
        g_idx1[warp] = i1;
        g_idx2[warp] = i2;
    }
}

// ---------------- scan: smem-resident ballot scans ----------------
__global__ void scan_kernel(float* __restrict__ out) {
    __shared__ uint8_t sidx1[S];
    __shared__ uint8_t sidx2[S];
    __shared__ short   sc1[S];
    __shared__ short   sc2[S];
    __shared__ float   red[256 * E];
    __shared__ int     sh_count1[E];
    __shared__ float   sh_me[E];

    int tid = threadIdx.x;
    int warp = tid >> 5;
    int lane = tid & 31;
    unsigned lt_mask = (lane == 0) ? 0u : (0xffffffffu >> (32 - lane));

    const int4* p1 = (const int4*)g_idx1;
    const int4* p2 = (const int4*)g_idx2;
    for (int i = tid; i < S / 4; i += 256) {
        int4 v = p1[i];
        sidx1[4 * i] = (uint8_t)v.x; sidx1[4 * i + 1] = (uint8_t)v.y;
        sidx1[4 * i + 2] = (uint8_t)v.z; sidx1[4 * i + 3] = (uint8_t)v.w;
        int4 u = p2[i];
        sidx2[4 * i] = (uint8_t)u.x; sidx2[4 * i + 1] = (uint8_t)u.y;
        sidx2[4 * i + 2] = (uint8_t)u.z; sidx2[4 * i + 3] = (uint8_t)u.w;
    }
    {
        float acc[E];
#pragma unroll
        for (int e = 0; e < E; e++) acc[e] = 0.0f;
        for (int s = tid; s < S; s += 256) {
            const float4* g = (const float4*)(g_gates + (size_t)s * E);
            float4 a = g[0], b = g[1];
            acc[0] += a.x; acc[1] += a.y; acc[2] += a.z; acc[3] += a.w;
            acc[4] += b.x; acc[5] += b.y; acc[6] += b.z; acc[7] += b.w;
        }
#pragma unroll
        for (int e = 0; e < E; e++) red[e * 256 + tid] = acc[e];
    }
    __syncthreads();
    {
        float v = 0.0f;
        for (int i = lane; i < 256; i += 32) v += red[warp * 256 + i];
#pragma unroll
        for (int off = 16; off > 0; off >>= 1) v += __shfl_down_sync(0xffffffffu, v, off);
        if (lane == 0) sh_me[warp] = v;
    }
    {
        int e = warp, rank = 0;
        for (int t0 = 0; t0 < S; t0 += 32) {
            int s = t0 + lane;
            int bit = (sidx1[s] == e);
            unsigned m = __ballot_sync(0xffffffffu, bit);
            if (bit) {
                int r = rank + __popc(m & lt_mask);
                if (r < CAP) { sc1[s] = (short)r; g_slot_tok[e * CAP + r] = s; }
                else         { sc1[s] = -1; }
            }
            rank += __popc(m);
        }
        if (lane == 0) sh_count1[e] = rank;
    }
    __syncthreads();
    {
        int e = warp, base = sh_count1[e], rank = 0;
        for (int t0 = 0; t0 < S; t0 += 32) {
            int s = t0 + lane;
            int bit = (sidx2[s] == e);
            unsigned m = __ballot_sync(0xffffffffu, bit);
            if (bit) {
                int r = base + rank + __popc(m & lt_mask);
                if (r < CAP) { sc2[s] = (short)r; g_slot_tok[e * CAP + r] = s; }
                else         { sc2[s] = -1; }
            }
            rank += __popc(m);
        }
    }
    __syncthreads();
    for (int s = tid; s < S; s += 256) {
        int i1 = sidx1[s], i2 = sidx2[s];
        int c1 = sc1[s], c2 = sc2[s];
        float g1 = (c1 >= 0) ? g_gates[(size_t)s * E + i1] : 0.0f;
        float g2 = (c2 >= 0) ? g_gates[(size_t)s * E + i2] : 0.0f;
        float denom = fmaxf(g1 + g2, 1.1920929e-7f);
        if (c1 >= 0) g_slot_w[i1 * CAP + c1] = g1 / denom;
        if (c2 >= 0) g_slot_w[i2 * CAP + c2] = g2 / denom;
    }
    if (tid == 0) {
        float laux = 0.0f;
        const float invS = 1.0f / (float)S;
#pragma unroll
        for (int e = 0; e < E; e++)
            laux += (sh_me[e] * invS) * ((float)sh_count1[e] * invS);
        laux = laux * (float)E * 0.01f;
        out[(size_t)S * H] = laux;
#pragma unroll
        for (int e = 0; e < E; e++)
            out[(size_t)S * H + 1 + e] = (float)sh_count1[e];
    }
}

// ---------------- fp16 GEMM: cp.async 4-stage, single sync per k-iter ----------------
// Block 128x128, BK=32, 8 warps (2M x 4N), warp tile 64x32. (round-11 proven config)
// MODE 1: A = g_xh gathered, C = g_h (fp16, GELU).
// MODE 2: A = g_h dense, epilogue = fused combine (atomicAdd into out).
template <int MODE>
__global__ void __launch_bounds__(256, 2)
hgemm_async(const __half* __restrict__ Ah, const __half* __restrict__ Bh,
            float* __restrict__ out, int K, int N,
            size_t sAe, size_t sBe, size_t sCe) {
    extern __shared__ __align__(16) char smem[];
    const uint32_t sb = smem_u32(smem);

    int tid = threadIdx.x;
    int e = blockIdx.z;
    int m0 = blockIdx.y * BM;
    int n0 = blockIdx.x * BN;
    const __half* Be = Bh + e * sBe;

    // ---- loader mapping ----
    int arow = tid >> 1;
    int acs  = (tid & 1) * 2;
    const __half* a_src;
    int asz = 16;
    if (MODE == 1) {
        int tok = g_slot_tok[e * CAP + m0 + arow];
        a_src = (tok >= 0) ? (Ah + (size_t)tok * K) : Ah;
        asz = (tok >= 0) ? 16 : 0;
    } else {
        a_src = Ah + e * sAe + (size_t)(m0 + arow) * K;
    }
    uint32_t a_dst = sb + (uint32_t)arow * ASTB + (uint32_t)acs * 16;
    int brow = tid >> 3;
    int bcs  = (tid & 7) * 2;
    const __half* b_src = Be + (size_t)brow * N + n0 + bcs * 8;
    uint32_t b_dst = sb + A_BYTES + (uint32_t)brow * BSTB + (uint32_t)bcs * 16;

    // ---- fragment mapping ----
    int w = tid >> 5, lane = tid & 31;
    int wm = (w >> 2) * 64;
    int wn = (w & 3) * 32;
    uint32_t a_frag = sb + (uint32_t)(wm + (lane & 15)) * ASTB + (uint32_t)(lane >> 4) * 16;
    uint32_t b_frag = sb + A_BYTES + (uint32_t)((lane & 7) + ((lane >> 3) & 1) * 8) * BSTB
                         + (uint32_t)(wn + (lane >> 4) * 8) * 2;

    float acc[4][4][4];
#pragma unroll
    for (int i = 0; i < 4; i++)
#pragma unroll
        for (int j = 0; j < 4; j++)
#pragma unroll
            for (int r = 0; r < 4; r++) acc[i][j][r] = 0.0f;

    int ntiles = K / BKT;

    auto load_stage = [&](int buf, int k0) {
        uint32_t so = (uint32_t)buf * STAGE;
        const __half* as = a_src + k0 + acs * 8;
        if (MODE == 1) {
            cp16z(a_dst + so, as, asz);
            cp16z(a_dst + so + 16, as + 8, asz);
        } else {
            cp16(a_dst + so, as);
            cp16(a_dst + so + 16, as + 8);
        }
        const __half* bs = b_src + (size_t)k0 * N;
        cp16(b_dst + so, bs);
        cp16(b_dst + so + 16, bs + 8);
    };

    load_stage(0, 0); cp_commit();
    load_stage(1, BKT); cp_commit();
    load_stage(2, 2 * BKT); cp_commit();

    for (int it = 0; it < ntiles; it++) {
        cp_wait<2>();
        __syncthreads();

        uint32_t so = (uint32_t)(it & 3) * STAGE;
#pragma unroll
        for (int ks = 0; ks < 2; ks++) {
            uint32_t af[4][4];
#pragma unroll
            for (int i = 0; i < 4; i++)
                ldsm4(af[i], a_frag + so + (uint32_t)i * (16 * ASTB) + ks * 32);
            uint32_t bf[4][2];
#pragma unroll
            for (int jp = 0; jp < 2; jp++) {
                uint32_t r[4];
                ldsm4t(r, b_frag + so + (uint32_t)ks * (16 * BSTB) + jp * 32);
                bf[2 * jp][0] = r[0]; bf[2 * jp][1] = r[1];
                bf[2 * jp + 1][0] = r[2]; bf[2 * jp + 1][1] = r[3];
            }
#pragma unroll
            for (int i = 0; i < 4; i++)
#pragma unroll
                for (int j = 0; j < 4; j++)
                    mma16816(acc[i][j], af[i], bf[j]);
        }

        if (it + 3 < ntiles) load_stage((it + 3) & 3, (it + 3) * BKT);
        cp_commit();
    }

    // ---- epilogue ----
    int gq = lane >> 2, tq = lane & 3;
    if (MODE == 1) {
        __half* Ch = g_h + e * sCe;
#pragma unroll
        for (int i = 0; i < 4; i++) {
            int row = m0 + wm + i * 16 + gq;
#pragma unroll
            for (int j = 0; j < 4; j++) {
                int col = n0 + wn + j * 8 + tq * 2;
                __half2 v0 = __floats2half2_rn(gelu_tanh(acc[i][j][0]), gelu_tanh(acc[i][j][1]));
                __half2 v1 = __floats2half2_rn(gelu_tanh(acc[i][j][2]), gelu_tanh(acc[i][j][3]));
                *reinterpret_cast<__half2*>(Ch + (size_t)row * N + col) = v0;
                *reinterpret_cast<__half2*>(Ch + (size_t)(row + 8) * N + col) = v1;
            }
        }
    } else {
#pragma unroll
        for (int i = 0; i < 4; i++) {
            int r0 = m0 + wm + i * 16 + gq;
            int s0 = e * CAP + r0;
            int t0 = g_slot_tok[s0], t1 = g_slot_tok[s0 + 8];
            float w0 = g_slot_w[s0], w1v = g_slot_w[s0 + 8];
            float* o0 = out + (size_t)t0 * H;
            float* o1 = out + (size_t)t1 * H;
#pragma unroll
            for (int j = 0; j < 4; j++) {
                int col = n0 + wn + j * 8 + tq * 2;
                if (t0 >= 0) {
                    atomicAdd(o0 + col,     w0 * acc[i][j][0]);
                    atomicAdd(o0 + col + 1, w0 * acc[i][j][1]);
                }
                if (t1 >= 0) {
                    atomicAdd(o1 + col,     w1v * acc[i][j][2]);
                    atomicAdd(o1 + col + 1, w1v * acc[i][j][3]);
                }
            }
        }
    }
}

// ---------------- launch ----------------
extern "C" void kernel_launch(void* const* d_in, const int* in_sizes, int n_in,
                              void* d_out, int out_size) {
    const float* x  = (const float*)d_in[0];
    const float* wg = (const float*)d_in[1];
    const float* w1 = (const float*)d_in[2];
    const float* w2 = (const float*)d_in[3];
    float* out = (float*)d_out;

    __half *xh, *w1h, *w2h, *hbuf;
    cudaGetSymbolAddress((void**)&xh,  g_xh);
    cudaGetSymbolAddress((void**)&w1h, g_w1h);
    cudaGetSymbolAddress((void**)&w2h, g_w2h);
    cudaGetSymbolAddress((void**)&hbuf, g_h);

    const int SMEM = NSTAGE * STAGE;   // 75776
    cudaFuncSetAttribute(hgemm_async<1>, cudaFuncAttributeMaxDynamicSharedMemorySize, SMEM);
    cudaFuncSetAttribute(hgemm_async<2>, cudaFuncAttributeMaxDynamicSharedMemorySize, SMEM);

    static cudaStream_t sA = nullptr;
    static cudaEvent_t eFork = nullptr, eW1 = nullptr, eW2 = nullptr;
    if (sA == nullptr) {
        cudaStreamCreateWithFlags(&sA, cudaStreamNonBlocking);
        cudaEventCreateWithFlags(&eFork, cudaEventDisableTiming);
        cudaEventCreateWithFlags(&eW1, cudaEventDisableTiming);
        cudaEventCreateWithFlags(&eW2, cudaEventDisableTiming);
    }

    const int NW4 = E * H * F / 4;

    // fork: w1 convert first (GEMM1's dependency), then w2 convert
    // (overlaps gate chain + GEMM1; only needed by GEMM2).
    cudaEventRecord(eFork, 0);
    cudaStreamWaitEvent(sA, eFork, 0);
    cvt_one<<<(NW4 + 255) / 256, 256, 0, sA>>>((const float4*)w1, (uint2*)w1h, NW4);
    cudaEventRecord(eW1, sA);
    cvt_one<<<(NW4 + 255) / 256, 256, 0, sA>>>((const float4*)w2, (uint2*)w2h, NW4);
    cudaEventRecord(eW2, sA);

    init_kernel<<<(S * H / 4 + 255) / 256, 256>>>((float4*)out);
    gate_kernel<<<S / 8, 256>>>(x, wg);
    scan_kernel<<<1, 256>>>(out);

    cudaStreamWaitEvent(0, eW1, 0);
    hgemm_async<1><<<dim3(F / BN, CAP / BM, E), 256, SMEM>>>(
        xh, w1h, nullptr, H, F, 0, (size_t)H * F, (size_t)CAP * F);

    cudaStreamWaitEvent(0, eW2, 0);
    hgemm_async<2><<<dim3(H / BN, CAP / BM, E), 256, SMEM>>>(
        hbuf, w2h, out, F, H, (size_t)CAP * F, (size_t)F * H, 0);
}

// round 16
// speedup vs baseline: 1.0137x; 1.0137x over previous
#include <cuda_runtime.h>
#include <cuda_fp16.h>
#include <math.h>
#include <stdint.h>

#define S 2048
#define H 1024
#define F 4096
#define E 8
#define CAP 512
#define BM 128
#define BN 128
#define BKT 32

// smem strides (bytes)
#define ASTB 80            // 32 halfs + 8 pad
#define BSTB 272           // 128 halfs + 8 pad
#define A_BYTES (BM * ASTB)            // 10240
#define STAGE (A_BYTES + BKT * BSTB)   // 18944
#define NSTAGE 4

__device__ float  g_gates[S * E];
__device__ int    g_idx1[S];
__device__ int    g_idx2[S];
__device__ int    g_slot_tok[E * CAP];
__device__ float  g_slot_w[E * CAP];
__device__ __half g_xh[(size_t)S * H];
__device__ __half g_w1h[(size_t)E * H * F];
__device__ __half g_w2h[(size_t)E * F * H];
__device__ __half g_h[(size_t)E * CAP * F];

// ---------------- helpers ----------------
__device__ __forceinline__ uint32_t smem_u32(const void* p) {
    uint32_t a;
    asm("{ .reg .u64 t; cvta.to.shared.u64 t, %1; cvt.u32.u64 %0, t; }" : "=r"(a) : "l"(p));
    return a;
}
__device__ __forceinline__ void cp16(uint32_t dst, const void* src) {
    asm volatile("cp.async.cg.shared.global [%0], [%1], 16;" :: "r"(dst), "l"(src));
}
__device__ __forceinline__ void cp16z(uint32_t dst, const void* src, int srcsize) {
    asm volatile("cp.async.cg.shared.global [%0], [%1], 16, %2;"
                 :: "r"(dst), "l"(src), "r"(srcsize));
}
__device__ __forceinline__ void cp_commit() {
    asm volatile("cp.async.commit_group;" ::: "memory");
}
template <int N> __device__ __forceinline__ void cp_wait() {
    asm volatile("cp.async.wait_group %0;" :: "n"(N) : "memory");
}
__device__ __forceinline__ void ldsm4(uint32_t* r, uint32_t a) {
    asm volatile("ldmatrix.sync.aligned.m8n8.x4.shared.b16 {%0,%1,%2,%3}, [%4];"
                 : "=r"(r[0]), "=r"(r[1]), "=r"(r[2]), "=r"(r[3]) : "r"(a));
}
__device__ __forceinline__ void ldsm4t(uint32_t* r, uint32_t a) {
    asm volatile("ldmatrix.sync.aligned.m8n8.x4.trans.shared.b16 {%0,%1,%2,%3}, [%4];"
                 : "=r"(r[0]), "=r"(r[1]), "=r"(r[2]), "=r"(r[3]) : "r"(a));
}
__device__ __forceinline__ void mma16816(float* c, const uint32_t* a, const uint32_t* b) {
    asm volatile(
        "mma.sync.aligned.m16n8k16.row.col.f32.f16.f16.f32 "
        "{%0,%1,%2,%3}, {%4,%5,%6,%7}, {%8,%9}, {%0,%1,%2,%3};"
        : "+f"(c[0]), "+f"(c[1]), "+f"(c[2]), "+f"(c[3])
        : "r"(a[0]), "r"(a[1]), "r"(a[2]), "r"(a[3]), "r"(b[0]), "r"(b[1]));
}
__device__ __forceinline__ float gelu_tanh(float v) {
    const float c = 0.7978845608028654f;
    float t = tanhf(c * (v + 0.044715f * v * v * v));
    return 0.5f * v * (1.0f + t);
}

// ---------------- fp32 -> fp16 convert (one tensor) ----------------
__global__ void cvt_one(const float4* __restrict__ src, uint2* __restrict__ dst, int n4) {
    int i = blockIdx.x * blockDim.x + threadIdx.x;
    if (i >= n4) return;
    float4 v = src[i];
    __half2 h0 = __floats2half2_rn(v.x, v.y);
    __half2 h1 = __floats2half2_rn(v.z, v.w);
    dst[i] = make_uint2(*reinterpret_cast<uint32_t*>(&h0), *reinterpret_cast<uint32_t*>(&h1));
}

// ---------------- init: slots -> -1, out -> 0 ----------------
__global__ void init_kernel(float4* __restrict__ out) {
    int i = blockIdx.x * blockDim.x + threadIdx.x;
    if (i < E * CAP) g_slot_tok[i] = -1;
    if (i < S * H / 4) out[i] = make_float4(0.f, 0.f, 0.f, 0.f);
}

// ---------------- gating: smem-transposed wg + float4 x (proven 14.7us) ----------------
__global__ void __launch_bounds__(256)
gate_kernel(const float* __restrict__ x, const float* __restrict__ wg) {
    __shared__ float swg[E * H];   // 32 KB, transposed [e][k]
    int tid = threadIdx.x;
    for (int i = tid; i < H * E; i += 256) {
        int k = i >> 3, e = i & 7;
        swg[e * H + k] = wg[i];
    }
    __syncthreads();

    int warp = blockIdx.x * 8 + (tid >> 5);
    int lane = tid & 31;
    const float4* xr4 = (const float4*)(x + (size_t)warp * H);
    uint2* xhr4 = (uint2*)(g_xh + (size_t)warp * H);

    float acc[E];
#pragma unroll
    for (int e = 0; e < E; e++) acc[e] = 0.0f;
#pragma unroll
    for (int it = 0; it < H / 128; it++) {
        int k4 = it * 32 + lane;
        float4 v = xr4[k4];
        __half2 h0 = __floats2half2_rn(v.x, v.y);
        __half2 h1 = __floats2half2_rn(v.z, v.w);
        xhr4[k4] = make_uint2(*reinterpret_cast<uint32_t*>(&h0),
                              *reinterpret_cast<uint32_t*>(&h1));
        int kk = 4 * k4;
#pragma unroll
        for (int e = 0; e < E; e++) {
            float4 wv = *reinterpret_cast<const float4*>(swg + e * H + kk);
            acc[e] += v.x * wv.x + v.y * wv.y + v.z * wv.z + v.w * wv.w;
        }
    }
#pragma unroll
    for (int off = 16; off > 0; off >>= 1)
#pragma unroll
        for (int e = 0; e < E; e++)
            acc[e] += __shfl_down_sync(0xffffffffu, acc[e], off);
    if (lane == 0) {
        float mx = acc[0];
#pragma unroll
        for (int e = 1; e < E; e++) mx = fmaxf(mx, acc[e]);
        float g[E], sum = 0.0f;
#pragma unroll
        for (int e = 0; e < E; e++) { g[e] = expf(acc[e] - mx); sum += g[e]; }
        float inv = 1.0f / sum;
        int i1 = 0; float v1 = acc[0];
#pragma unroll
        for (int e = 1; e < E; e++) if (acc[e] > v1) { v1 = acc[e]; i1 = e; }
        int i2 = -1; float v2 = -3.4e38f;
#pragma unroll
        for (int e = 0; e < E; e++)
            if (e != i1 && acc[e] > v2) { v2 = acc[e]; i2 = e; }
#pragma unroll
        for (int e = 0; e < E; e++) g_gates[warp * E + e] = g[e] * inv;
        g_idx1[warp] = i1;
        g_idx2[warp] = i2;
    }
}

// ---------------- scan: smem-resident ballot scans ----------------
__global__ void scan_kernel(float* __restrict__ out) {
    __shared__ uint8_t sidx1[S];
    __shared__ uint8_t sidx2[S];
    __shared__ short   sc1[S];
    __shared__ short   sc2[S];
    __shared__ float   red[256 * E];
    __shared__ int     sh_count1[E];
    __shared__ float   sh_me[E];

    int tid = threadIdx.x;
    int warp = tid >> 5;
    int lane = tid & 31;
    unsigned lt_mask = (lane == 0) ? 0u : (0xffffffffu >> (32 - lane));

    const int4* p1 = (const int4*)g_idx1;
    const int4* p2 = (const int4*)g_idx2;
    for (int i = tid; i < S / 4; i += 256) {
        int4 v = p1[i];
        sidx1[4 * i] = (uint8_t)v.x; sidx1[4 * i + 1] = (uint8_t)v.y;
        sidx1[4 * i + 2] = (uint8_t)v.z; sidx1[4 * i + 3] = (uint8_t)v.w;
        int4 u = p2[i];
        sidx2[4 * i] = (uint8_t)u.x; sidx2[4 * i + 1] = (uint8_t)u.y;
        sidx2[4 * i + 2] = (uint8_t)u.z; sidx2[4 * i + 3] = (uint8_t)u.w;
    }
    {
        float acc[E];
#pragma unroll
        for (int e = 0; e < E; e++) acc[e] = 0.0f;
        for (int s = tid; s < S; s += 256) {
            const float4* g = (const float4*)(g_gates + (size_t)s * E);
            float4 a = g[0], b = g[1];
            acc[0] += a.x; acc[1] += a.y; acc[2] += a.z; acc[3] += a.w;
            acc[4] += b.x; acc[5] += b.y; acc[6] += b.z; acc[7] += b.w;
        }
#pragma unroll
        for (int e = 0; e < E; e++) red[e * 256 + tid] = acc[e];
    }
    __syncthreads();
    {
        float v = 0.0f;
        for (int i = lane; i < 256; i += 32) v += red[warp * 256 + i];
#pragma unroll
        for (int off = 16; off > 0; off >>= 1) v += __shfl_down_sync(0xffffffffu, v, off);
        if (lane == 0) sh_me[warp] = v;
    }
    {
        int e = warp, rank = 0;
        for (int t0 = 0; t0 < S; t0 += 32) {
            int s = t0 + lane;
            int bit = (sidx1[s] == e);
            unsigned m = __ballot_sync(0xffffffffu, bit);
            if (bit) {
                int r = rank + __popc(m & lt_mask);
                if (r < CAP) { sc1[s] = (short)r; g_slot_tok[e * CAP + r] = s; }
                else         { sc1[s] = -1; }
            }
            rank += __popc(m);
        }
        if (lane == 0) sh_count1[e] = rank;
    }
    __syncthreads();
    {
        int e = warp, base = sh_count1[e], rank = 0;
        for (int t0 = 0; t0 < S; t0 += 32) {
            int s = t0 + lane;
            int bit = (sidx2[s] == e);
            unsigned m = __ballot_sync(0xffffffffu, bit);
            if (bit) {
                int r = base + rank + __popc(m & lt_mask);
                if (r < CAP) { sc2[s] = (short)r; g_slot_tok[e * CAP + r] = s; }
                else         { sc2[s] = -1; }
            }
            rank += __popc(m);
        }
    }
    __syncthreads();
    for (int s = tid; s < S; s += 256) {
        int i1 = sidx1[s], i2 = sidx2[s];
        int c1 = sc1[s], c2 = sc2[s];
        float g1 = (c1 >= 0) ? g_gates[(size_t)s * E + i1] : 0.0f;
        float g2 = (c2 >= 0) ? g_gates[(size_t)s * E + i2] : 0.0f;
        float denom = fmaxf(g1 + g2, 1.1920929e-7f);
        if (c1 >= 0) g_slot_w[i1 * CAP + c1] = g1 / denom;
        if (c2 >= 0) g_slot_w[i2 * CAP + c2] = g2 / denom;
    }
    if (tid == 0) {
        float laux = 0.0f;
        const float invS = 1.0f / (float)S;
#pragma unroll
        for (int e = 0; e < E; e++)
            laux += (sh_me[e] * invS) * ((float)sh_count1[e] * invS);
        laux = laux * (float)E * 0.01f;
        out[(size_t)S * H] = laux;
#pragma unroll
        for (int e = 0; e < E; e++)
            out[(size_t)S * H + 1 + e] = (float)sh_count1[e];
    }
}

// ---------------- fp16 GEMM: cp.async 4-stage, single sync per k-iter (round-11 proven) ----------------
// Block 128x128, BK=32, 8 warps (2M x 4N), warp tile 64x32.
// MODE 1: A = g_xh gathered, C = g_h (fp16, GELU).
// MODE 2: A = g_h dense, epilogue = fused combine (atomicAdd into out).
template <int MODE>
__global__ void __launch_bounds__(256, 2)
hgemm_async(const __half* __restrict__ Ah, const __half* __restrict__ Bh,
            float* __restrict__ out, int K, int N,
            size_t sAe, size_t sBe, size_t sCe) {
    extern __shared__ __align__(16) char smem[];
    const uint32_t sb = smem_u32(smem);

    int tid = threadIdx.x;
    int e = blockIdx.z;
    int m0 = blockIdx.y * BM;
    int n0 = blockIdx.x * BN;
    const __half* Be = Bh + e * sBe;

    // ---- loader mapping ----
    int arow = tid >> 1;
    int acs  = (tid & 1) * 2;
    const __half* a_src;
    int asz = 16;
    if (MODE == 1) {
        int tok = g_slot_tok[e * CAP + m0 + arow];
        a_src = (tok >= 0) ? (Ah + (size_t)tok * K) : Ah;
        asz = (tok >= 0) ? 16 : 0;
    } else {
        a_src = Ah + e * sAe + (size_t)(m0 + arow) * K;
    }
    uint32_t a_dst = sb + (uint32_t)arow * ASTB + (uint32_t)acs * 16;
    int brow = tid >> 3;
    int bcs  = (tid & 7) * 2;
    const __half* b_src = Be + (size_t)brow * N + n0 + bcs * 8;
    uint32_t b_dst = sb + A_BYTES + (uint32_t)brow * BSTB + (uint32_t)bcs * 16;

    // ---- fragment mapping ----
    int w = tid >> 5, lane = tid & 31;
    int wm = (w >> 2) * 64;
    int wn = (w & 3) * 32;
    uint32_t a_frag = sb + (uint32_t)(wm + (lane & 15)) * ASTB + (uint32_t)(lane >> 4) * 16;
    uint32_t b_frag = sb + A_BYTES + (uint32_t)((lane & 7) + ((lane >> 3) & 1) * 8) * BSTB
                         + (uint32_t)(wn + (lane >> 4) * 8) * 2;

    float acc[4][4][4];
#pragma unroll
    for (int i = 0; i < 4; i++)
#pragma unroll
        for (int j = 0; j < 4; j++)
#pragma unroll
            for (int r = 0; r < 4; r++) acc[i][j][r] = 0.0f;

    int ntiles = K / BKT;

    auto load_stage = [&](int buf, int k0) {
        uint32_t so = (uint32_t)buf * STAGE;
        const __half* as = a_src + k0 + acs * 8;
        if (MODE == 1) {
            cp16z(a_dst + so, as, asz);
            cp16z(a_dst + so + 16, as + 8, asz);
        } else {
            cp16(a_dst + so, as);
            cp16(a_dst + so + 16, as + 8);
        }
        const __half* bs = b_src + (size_t)k0 * N;
        cp16(b_dst + so, bs);
        cp16(b_dst + so + 16, bs + 8);
    };

    load_stage(0, 0); cp_commit();
    load_stage(1, BKT); cp_commit();
    load_stage(2, 2 * BKT); cp_commit();

    for (int it = 0; it < ntiles; it++) {
        cp_wait<2>();
        __syncthreads();

        uint32_t so = (uint32_t)(it & 3) * STAGE;
#pragma unroll
        for (int ks = 0; ks < 2; ks++) {
            uint32_t af[4][4];
#pragma unroll
            for (int i = 0; i < 4; i++)
                ldsm4(af[i], a_frag + so + (uint32_t)i * (16 * ASTB) + ks * 32);
            uint32_t bf[4][2];
#pragma unroll
            for (int jp = 0; jp < 2; jp++) {
                uint32_t r[4];
                ldsm4t(r, b_frag + so + (uint32_t)ks * (16 * BSTB) + jp * 32);
                bf[2 * jp][0] = r[0]; bf[2 * jp][1] = r[1];
                bf[2 * jp + 1][0] = r[2]; bf[2 * jp + 1][1] = r[3];
            }
#pragma unroll
            for (int i = 0; i < 4; i++)
#pragma unroll
                for (int j = 0; j < 4; j++)
                    mma16816(acc[i][j], af[i], bf[j]);
        }

        if (it + 3 < ntiles) load_stage((it + 3) & 3, (it + 3) * BKT);
        cp_commit();
    }

    // ---- epilogue ----
    int gq = lane >> 2, tq = lane & 3;
    if (MODE == 1) {
        __half* Ch = g_h + e * sCe;
#pragma unroll
        for (int i = 0; i < 4; i++) {
            int row = m0 + wm + i * 16 + gq;
#pragma unroll
            for (int j = 0; j < 4; j++) {
                int col = n0 + wn + j * 8 + tq * 2;
                __half2 v0 = __floats2half2_rn(gelu_tanh(acc[i][j][0]), gelu_tanh(acc[i][j][1]));
                __half2 v1 = __floats2half2_rn(gelu_tanh(acc[i][j][2]), gelu_tanh(acc[i][j][3]));
                *reinterpret_cast<__half2*>(Ch + (size_t)row * N + col) = v0;
                *reinterpret_cast<__half2*>(Ch + (size_t)(row + 8) * N + col) = v1;
            }
        }
    } else {
#pragma unroll
        for (int i = 0; i < 4; i++) {
            int r0 = m0 + wm + i * 16 + gq;
            int s0 = e * CAP + r0;
            int t0 = g_slot_tok[s0], t1 = g_slot_tok[s0 + 8];
            float w0 = g_slot_w[s0], w1v = g_slot_w[s0 + 8];
            float* o0 = out + (size_t)t0 * H;
            float* o1 = out + (size_t)t1 * H;
#pragma unroll
            for (int j = 0; j < 4; j++) {
                int col = n0 + wn + j * 8 + tq * 2;
                if (t0 >= 0) {
                    atomicAdd(o0 + col,     w0 * acc[i][j][0]);
                    atomicAdd(o0 + col + 1, w0 * acc[i][j][1]);
                }
                if (t1 >= 0) {
                    atomicAdd(o1 + col,     w1v * acc[i][j][2]);
                    atomicAdd(o1 + col + 1, w1v * acc[i][j][3]);
                }
            }
        }
    }
}

// ---------------- launch ----------------
extern "C" void kernel_launch(void* const* d_in, const int* in_sizes, int n_in,
                              void* d_out, int out_size) {
    const float* x  = (const float*)d_in[0];
    const float* wg = (const float*)d_in[1];
    const float* w1 = (const float*)d_in[2];
    const float* w2 = (const float*)d_in[3];
    float* out = (float*)d_out;

    __half *xh, *w1h, *w2h, *hbuf;
    cudaGetSymbolAddress((void**)&xh,  g_xh);
    cudaGetSymbolAddress((void**)&w1h, g_w1h);
    cudaGetSymbolAddress((void**)&w2h, g_w2h);
    cudaGetSymbolAddress((void**)&hbuf, g_h);

    const int SMEM = NSTAGE * STAGE;   // 75776
    cudaFuncSetAttribute(hgemm_async<1>, cudaFuncAttributeMaxDynamicSharedMemorySize, SMEM);
    cudaFuncSetAttribute(hgemm_async<2>, cudaFuncAttributeMaxDynamicSharedMemorySize, SMEM);

    // round-11 proven fork/join: PARALLEL converts, both done before GEMM1
    static cudaStream_t sA = nullptr, sB = nullptr;
    static cudaEvent_t eFork = nullptr, eW1 = nullptr, eW2 = nullptr;
    if (sA == nullptr) {
        cudaStreamCreateWithFlags(&sA, cudaStreamNonBlocking);
        cudaStreamCreateWithFlags(&sB, cudaStreamNonBlocking);
        cudaEventCreateWithFlags(&eFork, cudaEventDisableTiming);
        cudaEventCreateWithFlags(&eW1, cudaEventDisableTiming);
        cudaEventCreateWithFlags(&eW2, cudaEventDisableTiming);
    }

    const int NW4 = E * H * F / 4;

    cudaEventRecord(eFork, 0);
    cudaStreamWaitEvent(sA, eFork, 0);
    cudaStreamWaitEvent(sB, eFork, 0);
    cvt_one<<<(NW4 + 255) / 256, 256, 0, sA>>>((const float4*)w1, (uint2*)w1h, NW4);
    cvt_one<<<(NW4 + 255) / 256, 256, 0, sB>>>((const float4*)w2, (uint2*)w2h, NW4);
    cudaEventRecord(eW1, sA);
    cudaEventRecord(eW2, sB);

    init_kernel<<<(S * H / 4 + 255) / 256, 256>>>((float4*)out);
    gate_kernel<<<S / 8, 256>>>(x, wg);
    scan_kernel<<<1, 256>>>(out);

    cudaStreamWaitEvent(0, eW1, 0);
    hgemm_async<1><<<dim3(F / BN, CAP / BM, E), 256, SMEM>>>(
        xh, w1h, nullptr, H, F, 0, (size_t)H * F, (size_t)CAP * F);

    cudaStreamWaitEvent(0, eW2, 0);
    hgemm_async<2><<<dim3(H / BN, CAP / BM, E), 256, SMEM>>>(
        hbuf, w2h, out, F, H, (size_t)CAP * F, (size_t)F * H, 0);
}

// round 17
// speedup vs baseline: 1.3191x; 1.3012x over previous
#include <cuda_runtime.h>
#include <cuda_fp16.h>
#include <math.h>
#include <stdint.h>

#define S 2048
#define H 1024
#define F 4096
#define E 8
#define CAP 512
#define BM 128
#define BN 128
#define BKT 32

// smem strides (bytes)
#define ASTB 80            // 32 halfs + 8 pad
#define BSTB 272           // 128 halfs + 8 pad
#define A_BYTES (BM * ASTB)            // 10240
#define STAGE (A_BYTES + BKT * BSTB)   // 18944
#define NSTAGE 4

__device__ float  g_gates[S * E];
__device__ int    g_idx1[S];
__device__ int    g_idx2[S];
__device__ int    g_slot_tok[E * CAP];
__device__ float  g_slot_w[E * CAP];
__device__ __half g_xh[(size_t)S * H];
__device__ __half g_w1h[(size_t)E * H * F];
__device__ __half g_w2h[(size_t)E * F * H];
__device__ __half g_h[(size_t)E * CAP * F];

// ---------------- helpers ----------------
__device__ __forceinline__ uint32_t smem_u32(const void* p) {
    uint32_t a;
    asm("{ .reg .u64 t; cvta.to.shared.u64 t, %1; cvt.u32.u64 %0, t; }" : "=r"(a) : "l"(p));
    return a;
}
__device__ __forceinline__ void cp16(uint32_t dst, const void* src) {
    asm volatile("cp.async.cg.shared.global [%0], [%1], 16;" :: "r"(dst), "l"(src));
}
__device__ __forceinline__ void cp16z(uint32_t dst, const void* src, int srcsize) {
    asm volatile("cp.async.cg.shared.global [%0], [%1], 16, %2;"
                 :: "r"(dst), "l"(src), "r"(srcsize));
}
__device__ __forceinline__ void cp_commit() {
    asm volatile("cp.async.commit_group;" ::: "memory");
}
template <int N> __device__ __forceinline__ void cp_wait() {
    asm volatile("cp.async.wait_group %0;" :: "n"(N) : "memory");
}
__device__ __forceinline__ void ldsm4(uint32_t* r, uint32_t a) {
    asm volatile("ldmatrix.sync.aligned.m8n8.x4.shared.b16 {%0,%1,%2,%3}, [%4];"
                 : "=r"(r[0]), "=r"(r[1]), "=r"(r[2]), "=r"(r[3]) : "r"(a));
}
__device__ __forceinline__ void ldsm4t(uint32_t* r, uint32_t a) {
    asm volatile("ldmatrix.sync.aligned.m8n8.x4.trans.shared.b16 {%0,%1,%2,%3}, [%4];"
                 : "=r"(r[0]), "=r"(r[1]), "=r"(r[2]), "=r"(r[3]) : "r"(a));
}
__device__ __forceinline__ void mma16816(float* c, const uint32_t* a, const uint32_t* b) {
    asm volatile(
        "mma.sync.aligned.m16n8k16.row.col.f32.f16.f16.f32 "
        "{%0,%1,%2,%3}, {%4,%5,%6,%7}, {%8,%9}, {%0,%1,%2,%3};"
        : "+f"(c[0]), "+f"(c[1]), "+f"(c[2]), "+f"(c[3])
        : "r"(a[0]), "r"(a[1]), "r"(a[2]), "r"(a[3]), "r"(b[0]), "r"(b[1]));
}
__device__ __forceinline__ float gelu_tanh(float v) {
    const float c = 0.7978845608028654f;
    float t = tanhf(c * (v + 0.044715f * v * v * v));
    return 0.5f * v * (1.0f + t);
}

// ---------------- fp32 -> fp16 convert (one tensor) ----------------
__global__ void cvt_one(const float4* __restrict__ src, uint2* __restrict__ dst, int n4) {
    int i = blockIdx.x * blockDim.x + threadIdx.x;
    if (i >= n4) return;
    float4 v = src[i];
    __half2 h0 = __floats2half2_rn(v.x, v.y);
    __half2 h1 = __floats2half2_rn(v.z, v.w);
    dst[i] = make_uint2(*reinterpret_cast<uint32_t*>(&h0), *reinterpret_cast<uint32_t*>(&h1));
}

// ---------------- init: slots -> -1, out -> 0 ----------------
__global__ void init_kernel(float4* __restrict__ out) {
    int i = blockIdx.x * blockDim.x + threadIdx.x;
    if (i < E * CAP) g_slot_tok[i] = -1;
    if (i < S * H / 4) out[i] = make_float4(0.f, 0.f, 0.f, 0.f);
}

// ---------------- gating (round-11 scalar version; also emits fp16 x) ----------------
__global__ void gate_kernel(const float* __restrict__ x, const float* __restrict__ wg) {
    int warp = (blockIdx.x * blockDim.x + threadIdx.x) >> 5;
    int lane = threadIdx.x & 31;
    if (warp >= S) return;
    const float* xr = x + (size_t)warp * H;
    __half* xhr = g_xh + (size_t)warp * H;
    float acc[E];
#pragma unroll
    for (int e = 0; e < E; e++) acc[e] = 0.0f;
    for (int k = lane; k < H; k += 32) {
        float xv = xr[k];
        xhr[k] = __float2half_rn(xv);
        const float* wr = wg + (size_t)k * E;
#pragma unroll
        for (int e = 0; e < E; e++) acc[e] += xv * wr[e];
    }
#pragma unroll
    for (int off = 16; off > 0; off >>= 1)
#pragma unroll
        for (int e = 0; e < E; e++)
            acc[e] += __shfl_down_sync(0xffffffffu, acc[e], off);
    if (lane == 0) {
        float mx = acc[0];
#pragma unroll
        for (int e = 1; e < E; e++) mx = fmaxf(mx, acc[e]);
        float g[E], sum = 0.0f;
#pragma unroll
        for (int e = 0; e < E; e++) { g[e] = expf(acc[e] - mx); sum += g[e]; }
        float inv = 1.0f / sum;
        int i1 = 0; float v1 = acc[0];
#pragma unroll
        for (int e = 1; e < E; e++) if (acc[e] > v1) { v1 = acc[e]; i1 = e; }
        int i2 = -1; float v2 = -3.4e38f;
#pragma unroll
        for (int e = 0; e < E; e++)
            if (e != i1 && acc[e] > v2) { v2 = acc[e]; i2 = e; }
#pragma unroll
        for (int e = 0; e < E; e++) g_gates[warp * E + e] = g[e] * inv;
        g_idx1[warp] = i1;
        g_idx2[warp] = i2;
    }
}

// ---------------- scan: smem-resident ballot scans ----------------
__global__ void scan_kernel(float* __restrict__ out) {
    __shared__ uint8_t sidx1[S];
    __shared__ uint8_t sidx2[S];
    __shared__ short   sc1[S];
    __shared__ short   sc2[S];
    __shared__ float   red[256 * E];
    __shared__ int     sh_count1[E];
    __shared__ float   sh_me[E];

    int tid = threadIdx.x;
    int warp = tid >> 5;
    int lane = tid & 31;
    unsigned lt_mask = (lane == 0) ? 0u : (0xffffffffu >> (32 - lane));

    const int4* p1 = (const int4*)g_idx1;
    const int4* p2 = (const int4*)g_idx2;
    for (int i = tid; i < S / 4; i += 256) {
        int4 v = p1[i];
        sidx1[4 * i] = (uint8_t)v.x; sidx1[4 * i + 1] = (uint8_t)v.y;
        sidx1[4 * i + 2] = (uint8_t)v.z; sidx1[4 * i + 3] = (uint8_t)v.w;
        int4 u = p2[i];
        sidx2[4 * i] = (uint8_t)u.x; sidx2[4 * i + 1] = (uint8_t)u.y;
        sidx2[4 * i + 2] = (uint8_t)u.z; sidx2[4 * i + 3] = (uint8_t)u.w;
    }
    {
        float acc[E];
#pragma unroll
        for (int e = 0; e < E; e++) acc[e] = 0.0f;
        for (int s = tid; s < S; s += 256) {
            const float4* g = (const float4*)(g_gates + (size_t)s * E);
            float4 a = g[0], b = g[1];
            acc[0] += a.x; acc[1] += a.y; acc[2] += a.z; acc[3] += a.w;
            acc[4] += b.x; acc[5] += b.y; acc[6] += b.z; acc[7] += b.w;
        }
#pragma unroll
        for (int e = 0; e < E; e++) red[e * 256 + tid] = acc[e];
    }
    __syncthreads();
    {
        float v = 0.0f;
        for (int i = lane; i < 256; i += 32) v += red[warp * 256 + i];
#pragma unroll
        for (int off = 16; off > 0; off >>= 1) v += __shfl_down_sync(0xffffffffu, v, off);
        if (lane == 0) sh_me[warp] = v;
    }
    {
        int e = warp, rank = 0;
        for (int t0 = 0; t0 < S; t0 += 32) {
            int s = t0 + lane;
            int bit = (sidx1[s] == e);
            unsigned m = __ballot_sync(0xffffffffu, bit);
            if (bit) {
                int r = rank + __popc(m & lt_mask);
                if (r < CAP) { sc1[s] = (short)r; g_slot_tok[e * CAP + r] = s; }
                else         { sc1[s] = -1; }
            }
            rank += __popc(m);
        }
        if (lane == 0) sh_count1[e] = rank;
    }
    __syncthreads();
    {
        int e = warp, base = sh_count1[e], rank = 0;
        for (int t0 = 0; t0 < S; t0 += 32) {
            int s = t0 + lane;
            int bit = (sidx2[s] == e);
            unsigned m = __ballot_sync(0xffffffffu, bit);
            if (bit) {
                int r = base + rank + __popc(m & lt_mask);
                if (r < CAP) { sc2[s] = (short)r; g_slot_tok[e * CAP + r] = s; }
                else         { sc2[s] = -1; }
            }
            rank += __popc(m);
        }
    }
    __syncthreads();
    for (int s = tid; s < S; s += 256) {
        int i1 = sidx1[s], i2 = sidx2[s];
        int c1 = sc1[s], c2 = sc2[s];
        float g1 = (c1 >= 0) ? g_gates[(size_t)s * E + i1] : 0.0f;
        float g2 = (c2 >= 0) ? g_gates[(size_t)s * E + i2] : 0.0f;
        float denom = fmaxf(g1 + g2, 1.1920929e-7f);
        if (c1 >= 0) g_slot_w[i1 * CAP + c1] = g1 / denom;
        if (c2 >= 0) g_slot_w[i2 * CAP + c2] = g2 / denom;
    }
    if (tid == 0) {
        float laux = 0.0f;
        const float invS = 1.0f / (float)S;
#pragma unroll
        for (int e = 0; e < E; e++)
            laux += (sh_me[e] * invS) * ((float)sh_count1[e] * invS);
        laux = laux * (float)E * 0.01f;
        out[(size_t)S * H] = laux;
#pragma unroll
        for (int e = 0; e < E; e++)
            out[(size_t)S * H + 1 + e] = (float)sh_count1[e];
    }
}

// ---------------- fp16 GEMM: cp.async 4-stage, single sync per k-iter ----------------
// Block 128x128, BK=32, 8 warps (2M x 4N), warp tile 64x32.
// MODE 1: A = g_xh gathered, C = g_h (fp16, GELU).
// MODE 2: A = g_h dense, epilogue = fused combine (atomicAdd into out).
template <int MODE>
__global__ void __launch_bounds__(256, 2)
hgemm_async(const __half* __restrict__ Ah, const __half* __restrict__ Bh,
            float* __restrict__ out, int K, int N,
            size_t sAe, size_t sBe, size_t sCe) {
    extern __shared__ __align__(16) char smem[];
    const uint32_t sb = smem_u32(smem);

    int tid = threadIdx.x;
    int e = blockIdx.z;
    int m0 = blockIdx.y * BM;
    int n0 = blockIdx.x * BN;
    const __half* Be = Bh + e * sBe;

    // ---- loader mapping ----
    int arow = tid >> 1;
    int acs  = (tid & 1) * 2;
    const __half* a_src;
    int asz = 16;
    if (MODE == 1) {
        int tok = g_slot_tok[e * CAP + m0 + arow];
        a_src = (tok >= 0) ? (Ah + (size_t)tok * K) : Ah;
        asz = (tok >= 0) ? 16 : 0;
    } else {
        a_src = Ah + e * sAe + (size_t)(m0 + arow) * K;
    }
    uint32_t a_dst = sb + (uint32_t)arow * ASTB + (uint32_t)acs * 16;
    int brow = tid >> 3;
    int bcs  = (tid & 7) * 2;
    const __half* b_src = Be + (size_t)brow * N + n0 + bcs * 8;
    uint32_t b_dst = sb + A_BYTES + (uint32_t)brow * BSTB + (uint32_t)bcs * 16;

    // ---- fragment mapping ----
    int w = tid >> 5, lane = tid & 31;
    int wm = (w >> 2) * 64;
    int wn = (w & 3) * 32;
    uint32_t a_frag = sb + (uint32_t)(wm + (lane & 15)) * ASTB + (uint32_t)(lane >> 4) * 16;
    uint32_t b_frag = sb + A_BYTES + (uint32_t)((lane & 7) + ((lane >> 3) & 1) * 8) * BSTB
                         + (uint32_t)(wn + (lane >> 4) * 8) * 2;

    float acc[4][4][4];
#pragma unroll
    for (int i = 0; i < 4; i++)
#pragma unroll
        for (int j = 0; j < 4; j++)
#pragma unroll
            for (int r = 0; r < 4; r++) acc[i][j][r] = 0.0f;

    int ntiles = K / BKT;

    auto load_stage = [&](int buf, int k0) {
        uint32_t so = (uint32_t)buf * STAGE;
        const __half* as = a_src + k0 + acs * 8;
        if (MODE == 1) {
            cp16z(a_dst + so, as, asz);
            cp16z(a_dst + so + 16, as + 8, asz);
        } else {
            cp16(a_dst + so, as);
            cp16(a_dst + so + 16, as + 8);
        }
        const __half* bs = b_src + (size_t)k0 * N;
        cp16(b_dst + so, bs);
        cp16(b_dst + so + 16, bs + 8);
    };

    load_stage(0, 0); cp_commit();
    load_stage(1, BKT); cp_commit();
    load_stage(2, 2 * BKT); cp_commit();

    for (int it = 0; it < ntiles; it++) {
        cp_wait<2>();
        __syncthreads();

        uint32_t so = (uint32_t)(it & 3) * STAGE;
#pragma unroll
        for (int ks = 0; ks < 2; ks++) {
            uint32_t af[4][4];
#pragma unroll
            for (int i = 0; i < 4; i++)
                ldsm4(af[i], a_frag + so + (uint32_t)i * (16 * ASTB) + ks * 32);
            uint32_t bf[4][2];
#pragma unroll
            for (int jp = 0; jp < 2; jp++) {
                uint32_t r[4];
                ldsm4t(r, b_frag + so + (uint32_t)ks * (16 * BSTB) + jp * 32);
                bf[2 * jp][0] = r[0]; bf[2 * jp][1] = r[1];
                bf[2 * jp + 1][0] = r[2]; bf[2 * jp + 1][1] = r[3];
            }
#pragma unroll
            for (int i = 0; i < 4; i++)
#pragma unroll
                for (int j = 0; j < 4; j++)
                    mma16816(acc[i][j], af[i], bf[j]);
        }

        if (it + 3 < ntiles) load_stage((it + 3) & 3, (it + 3) * BKT);
        cp_commit();
    }

    // ---- epilogue ----
    int gq = lane >> 2, tq = lane & 3;
    if (MODE == 1) {
        __half* Ch = g_h + e * sCe;
#pragma unroll
        for (int i = 0; i < 4; i++) {
            int row = m0 + wm + i * 16 + gq;
#pragma unroll
            for (int j = 0; j < 4; j++) {
                int col = n0 + wn + j * 8 + tq * 2;
                __half2 v0 = __floats2half2_rn(gelu_tanh(acc[i][j][0]), gelu_tanh(acc[i][j][1]));
                __half2 v1 = __floats2half2_rn(gelu_tanh(acc[i][j][2]), gelu_tanh(acc[i][j][3]));
                *reinterpret_cast<__half2*>(Ch + (size_t)row * N + col) = v0;
                *reinterpret_cast<__half2*>(Ch + (size_t)(row + 8) * N + col) = v1;
            }
        }
    } else {
#pragma unroll
        for (int i = 0; i < 4; i++) {
            int r0 = m0 + wm + i * 16 + gq;
            int s0 = e * CAP + r0;
            int t0 = g_slot_tok[s0], t1 = g_slot_tok[s0 + 8];
            float w0 = g_slot_w[s0], w1v = g_slot_w[s0 + 8];
            float* o0 = out + (size_t)t0 * H;
            float* o1 = out + (size_t)t1 * H;
#pragma unroll
            for (int j = 0; j < 4; j++) {
                int col = n0 + wn + j * 8 + tq * 2;
                if (t0 >= 0) {
                    atomicAdd(o0 + col,     w0 * acc[i][j][0]);
                    atomicAdd(o0 + col + 1, w0 * acc[i][j][1]);
                }
                if (t1 >= 0) {
                    atomicAdd(o1 + col,     w1v * acc[i][j][2]);
                    atomicAdd(o1 + col + 1, w1v * acc[i][j][3]);
                }
            }
        }
    }
}

// ---------------- launch ----------------
extern "C" void kernel_launch(void* const* d_in, const int* in_sizes, int n_in,
                              void* d_out, int out_size) {
    const float* x  = (const float*)d_in[0];
    const float* wg = (const float*)d_in[1];
    const float* w1 = (const float*)d_in[2];
    const float* w2 = (const float*)d_in[3];
    float* out = (float*)d_out;

    __half *xh, *w1h, *w2h, *hbuf;
    cudaGetSymbolAddress((void**)&xh,  g_xh);
    cudaGetSymbolAddress((void**)&w1h, g_w1h);
    cudaGetSymbolAddress((void**)&w2h, g_w2h);
    cudaGetSymbolAddress((void**)&hbuf, g_h);

    const int SMEM = NSTAGE * STAGE;   // 75776
    cudaFuncSetAttribute(hgemm_async<1>, cudaFuncAttributeMaxDynamicSharedMemorySize, SMEM);
    cudaFuncSetAttribute(hgemm_async<2>, cudaFuncAttributeMaxDynamicSharedMemorySize, SMEM);

    static cudaStream_t sA = nullptr, sB = nullptr;
    static cudaEvent_t eFork = nullptr, eW1 = nullptr, eW2 = nullptr;
    if (sA == nullptr) {
        cudaStreamCreateWithFlags(&sA, cudaStreamNonBlocking);
        cudaStreamCreateWithFlags(&sB, cudaStreamNonBlocking);
        cudaEventCreateWithFlags(&eFork, cudaEventDisableTiming);
        cudaEventCreateWithFlags(&eW1, cudaEventDisableTiming);
        cudaEventCreateWithFlags(&eW2, cudaEventDisableTiming);
    }

    const int NW4 = E * H * F / 4;

    // fork: weight converts run concurrently with gating chain
    cudaEventRecord(eFork, 0);
    cudaStreamWaitEvent(sA, eFork, 0);
    cudaStreamWaitEvent(sB, eFork, 0);
    cvt_one<<<(NW4 + 255) / 256, 256, 0, sA>>>((const float4*)w1, (uint2*)w1h, NW4);
    cvt_one<<<(NW4 + 255) / 256, 256, 0, sB>>>((const float4*)w2, (uint2*)w2h, NW4);
    cudaEventRecord(eW1, sA);
    cudaEventRecord(eW2, sB);

    init_kernel<<<(S * H / 4 + 255) / 256, 256>>>((float4*)out);
    gate_kernel<<<(S * 32 + 255) / 256, 256>>>(x, wg);
    scan_kernel<<<1, 256>>>(out);

    cudaStreamWaitEvent(0, eW1, 0);
    hgemm_async<1><<<dim3(F / BN, CAP / BM, E), 256, SMEM>>>(
        xh, w1h, nullptr, H, F, 0, (size_t)H * F, (size_t)CAP * F);

    cudaStreamWaitEvent(0, eW2, 0);
    hgemm_async<2><<<dim3(H / BN, CAP / BM, E), 256, SMEM>>>(
        hbuf, w2h, out, F, H, (size_t)CAP * F, (size_t)F * H, 0);
}